// round 9
// baseline (speedup 1.0000x reference)
#include <cuda_runtime.h>
#include <cstdint>

#define NT 512
constexpr int Tn  = 16;
constexpr int Bn  = 16;
constexpr int Nn  = 1024;
constexpr int En  = 16384;
constexpr int Fin = 128;
constexpr int Hn  = 256;
constexpr int Kn  = 820;
constexpr int NG  = Tn * Bn;   // 256 graphs

// ---------------- global scratch ----------------
__device__ float g_emb[NG * Hn];

__device__ __forceinline__ float sigmoidf_(float v) { return 1.0f / (1.0f + expf(-v)); }

// ---------------- f32x2 helpers ----------------
__device__ __forceinline__ unsigned long long pk2(float a, float b) {
    unsigned long long r; asm("mov.b64 %0,{%1,%2};" : "=l"(r) : "f"(a), "f"(b)); return r;
}
__device__ __forceinline__ float2 upk(unsigned long long v) {
    float2 o; asm("mov.b64 {%0,%1},%2;" : "=f"(o.x), "=f"(o.y) : "l"(v)); return o;
}
__device__ __forceinline__ unsigned long long ffma2(unsigned long long a, unsigned long long b, unsigned long long c) {
    unsigned long long d; asm("fma.rn.f32x2 %0,%1,%2,%3;" : "=l"(d) : "l"(a), "l"(b), "l"(c)); return d;
}
__device__ __forceinline__ float hsum2(unsigned long long v) { float2 o = upk(v); return o.x + o.y; }

__device__ __forceinline__ uint32_t smem_u32(const void* p) {
    uint32_t a;
    asm("{ .reg .u64 t; cvta.to.shared.u64 t, %1; cvt.u32.u64 %0, t; }" : "=r"(a) : "l"(p));
    return a;
}

#define CLUSTER_SYNC_() do { \
    asm volatile("barrier.cluster.arrive.aligned;" ::: "memory"); \
    asm volatile("barrier.cluster.wait.aligned;" ::: "memory"); \
} while (0)

// wait (acquire, cluster scope) on local mbarrier phase parity
__device__ __forceinline__ void mbar_wait_par(uint32_t mbar, uint32_t parity) {
    asm volatile(
        "{\n\t.reg .pred P;\n\t"
        "WL_%=:\n\t"
        "mbarrier.try_wait.parity.acquire.cluster.shared::cta.b64 P, [%0], %1, 0x989680;\n\t"
        "@P bra.uni WD_%=;\n\t"
        "bra.uni WL_%=;\n\t"
        "WD_%=:\n\t}"
        :: "r"(mbar), "r"(parity) : "memory");
}

// conv1 half (f32x2): 256 threads (gt in [0,256)), nodes [pb, pb+512)
__device__ __forceinline__ void conv1_half(const float* __restrict__ xg,
                                           const unsigned long long* w1p,
                                           float* A, int gt, int pb)
{
    const int mq = gt & 3;
    const int nb = gt >> 2;
    const int c0 = mq * 4;
    for (int n = pb + nb; n < pb + 512; n += 64) {
        unsigned long long a0 = 0, a1 = 0, a2 = 0, a3 = 0;
        const ulonglong2* xr = (const ulonglong2*)(xg + (size_t)n * Fin);
        #pragma unroll 8
        for (int i = 0; i < 32; i++) {
            const ulonglong2 xv = xr[i];
            const ulonglong2* wp = (const ulonglong2*)&w1p[(2 * i) * 16 + c0];
            const ulonglong2* wq = (const ulonglong2*)&w1p[(2 * i + 1) * 16 + c0];
            const ulonglong2 wa = wp[0], wb = wp[1];
            const ulonglong2 wc = wq[0], wd = wq[1];
            a0 = ffma2(xv.x, wa.x, a0); a1 = ffma2(xv.x, wa.y, a1);
            a2 = ffma2(xv.x, wb.x, a2); a3 = ffma2(xv.x, wb.y, a3);
            a0 = ffma2(xv.y, wc.x, a0); a1 = ffma2(xv.y, wc.y, a1);
            a2 = ffma2(xv.y, wd.x, a2); a3 = ffma2(xv.y, wd.y, a3);
        }
        *(float4*)&A[n * 16 + c0] = make_float4(hsum2(a0), hsum2(a1), hsum2(a2), hsum2(a3));
    }
}

// =====================================================================
// K1: per-graph embedding. One CTA per graph. (verified R8 body)
// =====================================================================
__global__ __launch_bounds__(NT) void k_embed(
    const float* __restrict__ x, const int* __restrict__ ei,
    const float* __restrict__ W1, const float* __restrict__ b1,
    const float* __restrict__ Wl, const float* __restrict__ Wr,
    const float* __restrict__ sb,
    const float* __restrict__ W2, const float* __restrict__ b2)
{
    extern __shared__ float sm[];
    float*              A      = sm;                                 // [0,16384)
    float*              Bf     = sm + 16384;                         // [16384,32768)
    unsigned long long* keys   = (unsigned long long*)(sm + 32768);  // 1024 u64
    unsigned short*     srcs   = (unsigned short*)(sm + 34816);      // 16384 u16
    int*                off    = (int*)(sm + 43008);                 // 1028
    int*                cur    = (int*)(sm + 44036);                 // 1024
    float*              pv     = sm + 45060;                         // 1024
    float*              score  = sm + 46084;                         // 1024
    int*                newidx = (int*)(sm + 47108);                 // 1024
    float*              dinv2  = sm + 48132;                         // 1024
    unsigned long long* w1p    = (unsigned long long*)(sm + 49156);  // 1024 u64
    float*              w2s    = sm + 51204;                         // 4096 (aliases tmppos)
    unsigned char*      tmppos = (unsigned char*)(sm + 51204);       // 16384 u8
    float*              b2s    = sm + 55300;                         // 256
    float*              cst    = sm + 55556;                         // 64
    // total 55620 floats = 222480 B

    const int tid = threadIdx.x;
    const int g   = blockIdx.x;
    const float* xg   = x  + (size_t)g * Nn * Fin;
    const int*   srcp = ei + (size_t)g * 2 * En;
    const int*   dstp = srcp + En;

    for (int i = tid; i < 1024; i += NT) {
        const int f2 = i >> 4, c = i & 15;
        w1p[i] = pk2(W1[(2 * f2) * 16 + c], W1[(2 * f2 + 1) * 16 + c]);
    }
    if (tid < 16) { cst[tid] = b1[tid]; cst[16 + tid] = Wl[tid]; cst[32 + tid] = Wr[tid]; }
    if (tid == 0) cst[48] = sb[0];
    for (int i = tid; i < Nn; i += NT) cur[i] = 0;
    __syncthreads();

    // --- phase A: warps 0-7 conv1 nodes [0,512) || warps 8-15 histogram+rank
    if (tid < 256) {
        conv1_half(xg, w1p, A, tid, 0);
    } else {
        for (int e = tid - 256; e < En; e += 256)
            tmppos[e] = (unsigned char)atomicAdd(&cur[dstp[e]], 1);
    }
    __syncthreads();

    // --- exclusive Blelloch scan of counts -> off[0..1024] ------------------
    for (int i = tid; i < Nn; i += NT) off[i] = cur[i];
    for (int d2 = 1; d2 < Nn; d2 <<= 1) {
        __syncthreads();
        const int idx = (tid + 1) * (d2 << 1) - 1;
        if (idx < Nn) off[idx] += off[idx - d2];
    }
    __syncthreads();
    if (tid == 0) { off[Nn] = off[Nn - 1]; off[Nn - 1] = 0; }
    for (int d2 = Nn >> 1; d2 >= 1; d2 >>= 1) {
        __syncthreads();
        const int idx = (tid + 1) * (d2 << 1) - 1;
        if (idx < Nn) { const int t = off[idx - d2]; off[idx - d2] = off[idx]; off[idx] += t; }
    }
    __syncthreads();
    for (int i = tid; i < Nn; i += NT)
        pv[i] = rsqrtf(1.0f + (float)(off[i + 1] - off[i]));   // dinv
    __syncthreads();

    // --- phase C: warps 0-7 conv1 nodes [512,1024) || warps 8-15 placement --
    if (tid < 256) {
        conv1_half(xg, w1p, A, tid, 512);
    } else {
        for (int e = tid - 256; e < En; e += 256)
            srcs[off[dstp[e]] + tmppos[e]] = (unsigned short)srcp[e];
    }
    __syncthreads();

    // tmppos dead -> load W2/b2 into its alias; pre-scale A rows by dinv
    for (int i = tid; i < 16 * Hn; i += NT) w2s[i] = W2[i];
    for (int i = tid; i < Hn; i += NT) b2s[i] = b2[i];
    for (int i = tid; i < Nn * 16; i += NT) A[i] *= pv[i >> 4];
    __syncthreads();

    // --- conv1 gather (pure sum, self included) + bias + relu -> Bf = h1 ----
    {
        const int grp = tid >> 2, q = tid & 3;
        const float bx = cst[q * 4 + 0], by = cst[q * 4 + 1];
        const float bz = cst[q * 4 + 2], bw = cst[q * 4 + 3];
        for (int d = grp; d < Nn; d += 128) {
            const int e0 = off[d], e1 = off[d + 1];
            float4 ac = *(const float4*)&A[d * 16 + q * 4];
            for (int j = e0; j < e1; j++) {
                const float4 v = *(const float4*)&A[srcs[j] * 16 + q * 4];
                ac.x += v.x; ac.y += v.y; ac.z += v.z; ac.w += v.w;
            }
            const float dd = pv[d];
            float4 o;
            o.x = fmaxf(fmaf(ac.x, dd, bx), 0.f);
            o.y = fmaxf(fmaf(ac.y, dd, by), 0.f);
            o.z = fmaxf(fmaf(ac.z, dd, bz), 0.f);
            o.w = fmaxf(fmaf(ac.w, dd, bw), 0.f);
            *(float4*)&Bf[d * 16 + q * 4] = o;
        }
    }
    __syncthreads();

    // --- p[n] = h1[n].Wl ; score[n] = h1[n].Wr + sag_b ----------------------
    for (int n = tid; n < Nn; n += NT) {
        float pl = 0.f, pr = cst[48];
        #pragma unroll
        for (int m = 0; m < 16; m++) {
            const float h = Bf[n * 16 + m];
            pl = fmaf(h, cst[16 + m], pl);
            pr = fmaf(h, cst[32 + m], pr);
        }
        pv[n] = pl; score[n] = pr;
    }
    __syncthreads();

    // --- score[d] += sum p[srcs] ; sortable keys ------------------------------
    for (int d = tid; d < Nn; d += NT) {
        float s = score[d];
        const int e0 = off[d], e1 = off[d + 1];
        for (int j = e0; j < e1; j++) s += pv[srcs[j]];
        score[d] = s;
        unsigned u = __float_as_uint(s);
        u = (u & 0x80000000u) ? ~u : (u | 0x80000000u);
        keys[d] = ((unsigned long long)(~u) << 32) | (unsigned)d;
    }
    __syncthreads();

    // --- bitonic sort ----------------------------------------------------------
    for (int k = 2; k <= Nn; k <<= 1) {
        for (int j = k >> 1; j > 0; j >>= 1) {
            const int lo = ((tid & ~(j - 1)) << 1) | (tid & (j - 1));
            const int hi = lo + j;
            const unsigned long long a = keys[lo], b = keys[hi];
            const bool up = ((lo & k) == 0);
            if (up ? (a > b) : (a < b)) { keys[lo] = b; keys[hi] = a; }
            __syncthreads();
        }
    }

    // --- newidx + gate -----------------------------------------------------------
    for (int n = tid; n < Nn; n += NT) newidx[n] = -1;
    __syncthreads();
    float* tvf = (float*)cur;
    for (int r = tid; r < Kn; r += NT) {
        const int n = (int)(keys[r] & 0xFFFFFFFFull);
        newidx[n] = r;
        tvf[r] = tanhf(score[n]);
    }
    __syncthreads();
    for (int i = tid; i < Kn * 16; i += NT) {
        const int r = i >> 4, m = i & 15;
        const int n = (int)(keys[r] & 0xFFFFFFFFull);
        A[r * 16 + m] = Bf[n * 16 + m] * tvf[r];
    }
    __syncthreads();

    // --- deg2 over valid remapped edges -----------------------------------------
    for (int d = tid; d < Nn; d += NT) {
        const int nd = newidx[d];
        if (nd >= 0) {
            int c = 0;
            const int e0 = off[d], e1 = off[d + 1];
            for (int j = e0; j < e1; j++) c += (newidx[srcs[j]] >= 0);
            dinv2[nd] = rsqrtf(1.0f + (float)c);
        }
    }
    __syncthreads();
    for (int i = tid; i < Kn * 16; i += NT) A[i] *= dinv2[i >> 4];
    __syncthreads();

    // --- conv2 pre-aggregation (MID space) -> Bf rows [0,K) ----------------------
    {
        const int grp = tid >> 2, q = tid & 3;
        for (int d = grp; d < Nn; d += 128) {
            const int nd = newidx[d];
            if (nd < 0) continue;
            const int e0 = off[d], e1 = off[d + 1];
            float4 ac = *(const float4*)&A[nd * 16 + q * 4];
            for (int j = e0; j < e1; j++) {
                const int ns = newidx[srcs[j]];
                if (ns >= 0) {
                    const float4 v = *(const float4*)&A[ns * 16 + q * 4];
                    ac.x += v.x; ac.y += v.y; ac.z += v.z; ac.w += v.w;
                }
            }
            const float dd = dinv2[nd];
            *(float4*)&Bf[nd * 16 + q * 4] = make_float4(ac.x * dd, ac.y * dd, ac.z * dd, ac.w * dd);
        }
    }
    __syncthreads();

    // --- h2 = relu(pre @ W2 + b2), mean over K -> g_emb (f32x2, regs) ------------
    {
        const int cg = tid & 63, rb = tid >> 6;
        const int c0 = cg * 4;
        unsigned long long wreg[32];
        #pragma unroll
        for (int i = 0; i < 4; i++)
            #pragma unroll
            for (int k2 = 0; k2 < 8; k2++)
                wreg[i * 8 + k2] = pk2(w2s[(2 * k2) * Hn + c0 + i], w2s[(2 * k2 + 1) * Hn + c0 + i]);
        float biasv[4], accs[4];
        #pragma unroll
        for (int i = 0; i < 4; i++) { biasv[i] = b2s[c0 + i]; accs[i] = 0.f; }

        for (int r = rb; r < Kn; r += 8) {
            const ulonglong2* pr = (const ulonglong2*)&Bf[r * 16];
            const ulonglong2 v0 = pr[0], v1 = pr[1], v2 = pr[2], v3 = pr[3];
            #pragma unroll
            for (int i = 0; i < 4; i++) {
                unsigned long long dd_ = 0;
                dd_ = ffma2(v0.x, wreg[i * 8 + 0], dd_);
                dd_ = ffma2(v0.y, wreg[i * 8 + 1], dd_);
                dd_ = ffma2(v1.x, wreg[i * 8 + 2], dd_);
                dd_ = ffma2(v1.y, wreg[i * 8 + 3], dd_);
                dd_ = ffma2(v2.x, wreg[i * 8 + 4], dd_);
                dd_ = ffma2(v2.y, wreg[i * 8 + 5], dd_);
                dd_ = ffma2(v3.x, wreg[i * 8 + 6], dd_);
                dd_ = ffma2(v3.y, wreg[i * 8 + 7], dd_);
                accs[i] += fmaxf(hsum2(dd_) + biasv[i], 0.f);
            }
        }
        float* redf = (float*)keys;
        #pragma unroll
        for (int i = 0; i < 4; i++) redf[rb * 256 + c0 + i] = accs[i];
        __syncthreads();
        if (tid < 256) {
            float s = 0.f;
            #pragma unroll
            for (int rbi = 0; rbi < 8; rbi++) s += redf[rbi * 256 + tid];
            g_emb[(size_t)g * Hn + tid] = s * (1.0f / (float)Kn);
        }
    }
}

// =====================================================================
// K2: LSTM, 16 clusters of 8 CTAs (one per batch). NO barrier.cluster in
// the time loop: per-step sync via mbarrier arrive(release)/try_wait.
// Warp w owns hidden units {2w, 2w+1} (gate rows 8w..8w+8) — all intra-warp.
// =====================================================================
__global__ __launch_bounds__(512) __cluster_dims__(8, 1, 1)
void k_lstm(const float* __restrict__ W_ih, const float* __restrict__ b_ih,
            const float* __restrict__ b_hh, const float* __restrict__ W_hh,
            const float* __restrict__ cls_W, const float* __restrict__ cls_b,
            float* __restrict__ out)
{
    __shared__ float hsb[2 * 288];        // [buf][(k>>5)*36 + (k&31)]
    __shared__ float iht[Tn * 32 * 4];    // [(t*32+hu_l)*4 + gate]
    __shared__ float embt[Tn * 260];      // emb rows for this batch
    __shared__ float bsm[128];
    __shared__ __align__(8) unsigned long long mb;

    const int tid = threadIdx.x;
    uint32_t rank; asm("mov.u32 %0, %%cluster_ctarank;" : "=r"(rank));
    const int b  = blockIdx.x >> 3;       // batch = cluster id
    const int kc = tid & 7;               // k-chunk [32kc, 32kc+32)
    const int jp = tid >> 3;              // rows {2jp, 2jp+1}
    const int q0 = 2 * jp, q1 = 2 * jp + 1;
    const int j0 = (q0 & 3) * Hn + (int)rank * 32 + (q0 >> 2);
    const int j1 = (q1 & 3) * Hn + (int)rank * 32 + (q1 >> 2);
    const uint32_t mbaddr = smem_u32(&mb);

    // --- stage emb rows for this batch: graph g = t*16 + b -------------------
    for (int idx = tid; idx < Tn * Hn; idx += 512) {
        const int t = idx >> 8, k = idx & 255;
        embt[t * 260 + k] = g_emb[(size_t)(t * Bn + b) * Hn + k];
    }
    if (tid < 128) bsm[tid] = b_ih[(tid & 3) * Hn + (int)rank * 32 + (tid >> 2)]
                            + b_hh[(tid & 3) * Hn + (int)rank * 32 + (tid >> 2)];
    for (int i = tid; i < 288; i += 512) hsb[i] = 0.f;   // buf0 = h(0) = 0
    if (tid == 0)
        asm volatile("mbarrier.init.shared.b64 [%0], %1;" :: "r"(mbaddr), "r"(256u) : "memory");

    unsigned long long wA[16], wB[16];
    // --- phase 1: wA/wB = W_ih rows; compute iht ------------------------------
    {
        const float* r0 = W_ih + (size_t)j0 * Hn + kc * 32;
        const float* r1 = W_ih + (size_t)j1 * Hn + kc * 32;
        #pragma unroll
        for (int i = 0; i < 16; i++) {
            wA[i] = pk2(r0[2 * i], r0[2 * i + 1]);
            wB[i] = pk2(r1[2 * i], r1[2 * i + 1]);
        }
    }
    __syncthreads();
    for (int t = 0; t < Tn; t++) {
        const ulonglong2* ev = (const ulonglong2*)&embt[t * 260 + kc * 32];
        unsigned long long aA = 0, aB = 0;
        #pragma unroll
        for (int i2 = 0; i2 < 8; i2++) {
            const ulonglong2 e2 = ev[i2];
            aA = ffma2(e2.x, wA[2 * i2],     aA);
            aA = ffma2(e2.y, wA[2 * i2 + 1], aA);
            aB = ffma2(e2.x, wB[2 * i2],     aB);
            aB = ffma2(e2.y, wB[2 * i2 + 1], aB);
        }
        float fA = hsum2(aA), fB = hsum2(aB);
        fA += __shfl_xor_sync(0xFFFFFFFFu, fA, 1);
        fA += __shfl_xor_sync(0xFFFFFFFFu, fA, 2);
        fA += __shfl_xor_sync(0xFFFFFFFFu, fA, 4);
        fB += __shfl_xor_sync(0xFFFFFFFFu, fB, 1);
        fB += __shfl_xor_sync(0xFFFFFFFFu, fB, 2);
        fB += __shfl_xor_sync(0xFFFFFFFFu, fB, 4);
        if (kc == 0) {
            iht[(t * 32 + (q0 >> 2)) * 4 + (q0 & 3)] = fA + bsm[q0];
            iht[(t * 32 + (q1 >> 2)) * 4 + (q1 & 3)] = fB + bsm[q1];
        }
    }

    // --- phase 2: wA/wB = W_hh rows -------------------------------------------
    {
        const float* r0 = W_hh + (size_t)j0 * Hn + kc * 32;
        const float* r1 = W_hh + (size_t)j1 * Hn + kc * 32;
        #pragma unroll
        for (int i = 0; i < 16; i++) {
            wA[i] = pk2(r0[2 * i], r0[2 * i + 1]);
            wB[i] = pk2(r1[2 * i], r1[2 * i + 1]);
        }
    }
    __syncthreads();
    CLUSTER_SYNC_();   // mbarrier init visible cluster-wide before any arrive

    const int lane = tid & 31;
    const int warp = tid >> 5;
    const bool epi = ((lane & 15) == 0);           // lanes 0 and 16
    const int  ehu = 2 * warp + (lane >> 4);       // local hidden unit
    float creg = 0.f;

    for (int t = 0; t < Tn; t++) {
        const ulonglong2* hv = (const ulonglong2*)&hsb[(t & 1) * 288 + kc * 36];
        unsigned long long aA = 0, aB = 0;
        #pragma unroll
        for (int i2 = 0; i2 < 8; i2++) {
            const ulonglong2 h2 = hv[i2];
            aA = ffma2(h2.x, wA[2 * i2],     aA);
            aA = ffma2(h2.y, wA[2 * i2 + 1], aA);
            aB = ffma2(h2.x, wB[2 * i2],     aB);
            aB = ffma2(h2.y, wB[2 * i2 + 1], aB);
        }
        float fA = hsum2(aA), fB = hsum2(aB);
        fA += __shfl_xor_sync(0xFFFFFFFFu, fA, 1);
        fA += __shfl_xor_sync(0xFFFFFFFFu, fA, 2);
        fA += __shfl_xor_sync(0xFFFFFFFFu, fA, 4);
        fB += __shfl_xor_sync(0xFFFFFFFFu, fB, 1);
        fB += __shfl_xor_sync(0xFFFFFFFFu, fB, 2);
        fB += __shfl_xor_sync(0xFFFFFFFFu, fB, 4);

        // gather 4 gates to lanes 0 (hu 2w) and 16 (hu 2w+1)
        const int base = lane & 16;
        const float gi = __shfl_sync(0xFFFFFFFFu, fA, base);
        const float gf = __shfl_sync(0xFFFFFFFFu, fB, base);
        const float gg = __shfl_sync(0xFFFFFFFFu, fA, base + 8);
        const float go = __shfl_sync(0xFFFFFFFFu, fB, base + 8);

        if (epi) {
            const float4 ihv = *(const float4*)&iht[(t * 32 + ehu) * 4];
            creg = sigmoidf_(gf + ihv.y) * creg + sigmoidf_(gi + ihv.x) * tanhf(gg + ihv.z);
            const float hn = sigmoidf_(go + ihv.w) * tanhf(creg);
            const uint32_t laddr =
                smem_u32(&hsb[((t + 1) & 1) * 288 + (int)rank * 36 + ehu]);
            #pragma unroll
            for (int dr = 0; dr < 8; dr++) {
                uint32_t ra;
                asm("mapa.shared::cluster.u32 %0, %1, %2;" : "=r"(ra) : "r"(laddr), "r"(dr));
                asm volatile("st.shared::cluster.f32 [%0], %1;" :: "r"(ra), "f"(hn) : "memory");
            }
            asm volatile("fence.acq_rel.cluster;" ::: "memory");
            #pragma unroll
            for (int dr = 0; dr < 8; dr++) {
                uint32_t ra;
                asm("mapa.shared::cluster.u32 %0, %1, %2;" : "=r"(ra) : "r"(mbaddr), "r"(dr));
                asm volatile("mbarrier.arrive.release.cluster.shared::cluster.b64 _, [%0];"
                             :: "r"(ra) : "memory");
            }
        }
        mbar_wait_par(mbaddr, (uint32_t)(t & 1));
    }

    // final h (h(16)) in hsb buf 0 of every CTA; rank 0 classifies its batch
    if (rank == 0 && tid < 32) {
        float p = 0.f;
        #pragma unroll
        for (int i = 0; i < 8; i++)
            p += hsb[i * 36 + tid] * __ldg(&cls_W[i * 32 + tid]);
        #pragma unroll
        for (int o = 16; o; o >>= 1) p += __shfl_xor_sync(0xFFFFFFFFu, p, o);
        if (tid == 0) out[b] = p + cls_b[0];
    }
    CLUSTER_SYNC_();   // keep cluster smem alive until all remote ops done
}

// =====================================================================
extern "C" void kernel_launch(void* const* d_in, const int* in_sizes, int n_in,
                              void* d_out, int out_size)
{
    (void)in_sizes; (void)n_in; (void)out_size;
    const float* x     = (const float*)d_in[0];
    const int*   ei    = (const int*)  d_in[1];
    const float* W1    = (const float*)d_in[2];
    const float* b1    = (const float*)d_in[3];
    const float* Wl    = (const float*)d_in[4];
    const float* Wr    = (const float*)d_in[5];
    const float* sb    = (const float*)d_in[6];
    const float* W2    = (const float*)d_in[7];
    const float* b2    = (const float*)d_in[8];
    const float* W_ih  = (const float*)d_in[9];
    const float* W_hh  = (const float*)d_in[10];
    const float* b_ih  = (const float*)d_in[11];
    const float* b_hh  = (const float*)d_in[12];
    const float* cls_W = (const float*)d_in[13];
    const float* cls_b = (const float*)d_in[14];
    float* out = (float*)d_out;

    const size_t smem1 = 55620 * sizeof(float);  // 222480 B
    cudaFuncSetAttribute(k_embed, cudaFuncAttributeMaxDynamicSharedMemorySize, (int)smem1);

    k_embed<<<NG, NT, smem1>>>(x, ei, W1, b1, Wl, Wr, sb, W2, b2);
    k_lstm <<<128, 512>>>(W_ih, b_ih, b_hh, W_hh, cls_W, cls_b, out);
}

// round 10
// speedup vs baseline: 1.4042x; 1.4042x over previous
#include <cuda_runtime.h>
#include <cstdint>

#define NT 512
constexpr int Tn  = 16;
constexpr int Bn  = 16;
constexpr int Nn  = 1024;
constexpr int En  = 16384;
constexpr int Fin = 128;
constexpr int Hn  = 256;
constexpr int Kn  = 820;
constexpr int NG  = Tn * Bn;   // 256 graphs

// ---------------- global scratch ----------------
__device__ float    g_emb[NG * Hn];
__device__ float    g_h[2 * Bn * Hn];     // double-buffered hidden state
__device__ unsigned g_cnt[Bn * Tn];       // per-batch per-step arrival counters

__device__ __forceinline__ float sigmoidf_(float v) { return 1.0f / (1.0f + expf(-v)); }

// ---------------- f32x2 helpers ----------------
__device__ __forceinline__ unsigned long long pk2(float a, float b) {
    unsigned long long r; asm("mov.b64 %0,{%1,%2};" : "=l"(r) : "f"(a), "f"(b)); return r;
}
__device__ __forceinline__ float2 upk(unsigned long long v) {
    float2 o; asm("mov.b64 {%0,%1},%2;" : "=f"(o.x), "=f"(o.y) : "l"(v)); return o;
}
__device__ __forceinline__ unsigned long long ffma2(unsigned long long a, unsigned long long b, unsigned long long c) {
    unsigned long long d; asm("fma.rn.f32x2 %0,%1,%2,%3;" : "=l"(d) : "l"(a), "l"(b), "l"(c)); return d;
}
__device__ __forceinline__ float hsum2(unsigned long long v) { float2 o = upk(v); return o.x + o.y; }

// conv1 half (f32x2): 256 threads (gt in [0,256)), nodes [pb, pb+512)
__device__ __forceinline__ void conv1_half(const float* __restrict__ xg,
                                           const unsigned long long* w1p,
                                           float* A, int gt, int pb)
{
    const int mq = gt & 3;
    const int nb = gt >> 2;
    const int c0 = mq * 4;
    for (int n = pb + nb; n < pb + 512; n += 64) {
        unsigned long long a0 = 0, a1 = 0, a2 = 0, a3 = 0;
        const ulonglong2* xr = (const ulonglong2*)(xg + (size_t)n * Fin);
        #pragma unroll 8
        for (int i = 0; i < 32; i++) {
            const ulonglong2 xv = xr[i];
            const ulonglong2* wp = (const ulonglong2*)&w1p[(2 * i) * 16 + c0];
            const ulonglong2* wq = (const ulonglong2*)&w1p[(2 * i + 1) * 16 + c0];
            const ulonglong2 wa = wp[0], wb = wp[1];
            const ulonglong2 wc = wq[0], wd = wq[1];
            a0 = ffma2(xv.x, wa.x, a0); a1 = ffma2(xv.x, wa.y, a1);
            a2 = ffma2(xv.x, wb.x, a2); a3 = ffma2(xv.x, wb.y, a3);
            a0 = ffma2(xv.y, wc.x, a0); a1 = ffma2(xv.y, wc.y, a1);
            a2 = ffma2(xv.y, wd.x, a2); a3 = ffma2(xv.y, wd.y, a3);
        }
        *(float4*)&A[n * 16 + c0] = make_float4(hsum2(a0), hsum2(a1), hsum2(a2), hsum2(a3));
    }
}

// =====================================================================
// K1: per-graph embedding. One CTA per graph. (verified R8 body;
// only change: block 0 also zeroes g_cnt)
// =====================================================================
__global__ __launch_bounds__(NT) void k_embed(
    const float* __restrict__ x, const int* __restrict__ ei,
    const float* __restrict__ W1, const float* __restrict__ b1,
    const float* __restrict__ Wl, const float* __restrict__ Wr,
    const float* __restrict__ sb,
    const float* __restrict__ W2, const float* __restrict__ b2)
{
    extern __shared__ float sm[];
    float*              A      = sm;                                 // [0,16384)
    float*              Bf     = sm + 16384;                         // [16384,32768)
    unsigned long long* keys   = (unsigned long long*)(sm + 32768);  // 1024 u64
    unsigned short*     srcs   = (unsigned short*)(sm + 34816);      // 16384 u16
    int*                off    = (int*)(sm + 43008);                 // 1028
    int*                cur    = (int*)(sm + 44036);                 // 1024
    float*              pv     = sm + 45060;                         // 1024
    float*              score  = sm + 46084;                         // 1024
    int*                newidx = (int*)(sm + 47108);                 // 1024
    float*              dinv2  = sm + 48132;                         // 1024
    unsigned long long* w1p    = (unsigned long long*)(sm + 49156);  // 1024 u64
    float*              w2s    = sm + 51204;                         // 4096 (aliases tmppos)
    unsigned char*      tmppos = (unsigned char*)(sm + 51204);       // 16384 u8
    float*              b2s    = sm + 55300;                         // 256
    float*              cst    = sm + 55556;                         // 64
    // total 55620 floats = 222480 B

    const int tid = threadIdx.x;
    const int g   = blockIdx.x;
    const float* xg   = x  + (size_t)g * Nn * Fin;
    const int*   srcp = ei + (size_t)g * 2 * En;
    const int*   dstp = srcp + En;

    for (int i = tid; i < 1024; i += NT) {
        const int f2 = i >> 4, c = i & 15;
        w1p[i] = pk2(W1[(2 * f2) * 16 + c], W1[(2 * f2 + 1) * 16 + c]);
    }
    if (tid < 16) { cst[tid] = b1[tid]; cst[16 + tid] = Wl[tid]; cst[32 + tid] = Wr[tid]; }
    if (tid == 0) cst[48] = sb[0];
    for (int i = tid; i < Nn; i += NT) cur[i] = 0;
    if (g == 0 && tid < Bn * Tn) g_cnt[tid] = 0u;
    __syncthreads();

    // --- phase A: warps 0-7 conv1 nodes [0,512) || warps 8-15 histogram+rank
    if (tid < 256) {
        conv1_half(xg, w1p, A, tid, 0);
    } else {
        for (int e = tid - 256; e < En; e += 256)
            tmppos[e] = (unsigned char)atomicAdd(&cur[dstp[e]], 1);
    }
    __syncthreads();

    // --- exclusive Blelloch scan of counts -> off[0..1024] ------------------
    for (int i = tid; i < Nn; i += NT) off[i] = cur[i];
    for (int d2 = 1; d2 < Nn; d2 <<= 1) {
        __syncthreads();
        const int idx = (tid + 1) * (d2 << 1) - 1;
        if (idx < Nn) off[idx] += off[idx - d2];
    }
    __syncthreads();
    if (tid == 0) { off[Nn] = off[Nn - 1]; off[Nn - 1] = 0; }
    for (int d2 = Nn >> 1; d2 >= 1; d2 >>= 1) {
        __syncthreads();
        const int idx = (tid + 1) * (d2 << 1) - 1;
        if (idx < Nn) { const int t = off[idx - d2]; off[idx - d2] = off[idx]; off[idx] += t; }
    }
    __syncthreads();
    for (int i = tid; i < Nn; i += NT)
        pv[i] = rsqrtf(1.0f + (float)(off[i + 1] - off[i]));   // dinv
    __syncthreads();

    // --- phase C: warps 0-7 conv1 nodes [512,1024) || warps 8-15 placement --
    if (tid < 256) {
        conv1_half(xg, w1p, A, tid, 512);
    } else {
        for (int e = tid - 256; e < En; e += 256)
            srcs[off[dstp[e]] + tmppos[e]] = (unsigned short)srcp[e];
    }
    __syncthreads();

    // tmppos dead -> load W2/b2 into its alias; pre-scale A rows by dinv
    for (int i = tid; i < 16 * Hn; i += NT) w2s[i] = W2[i];
    for (int i = tid; i < Hn; i += NT) b2s[i] = b2[i];
    for (int i = tid; i < Nn * 16; i += NT) A[i] *= pv[i >> 4];
    __syncthreads();

    // --- conv1 gather (pure sum, self included) + bias + relu -> Bf = h1 ----
    {
        const int grp = tid >> 2, q = tid & 3;
        const float bx = cst[q * 4 + 0], by = cst[q * 4 + 1];
        const float bz = cst[q * 4 + 2], bw = cst[q * 4 + 3];
        for (int d = grp; d < Nn; d += 128) {
            const int e0 = off[d], e1 = off[d + 1];
            float4 ac = *(const float4*)&A[d * 16 + q * 4];
            for (int j = e0; j < e1; j++) {
                const float4 v = *(const float4*)&A[srcs[j] * 16 + q * 4];
                ac.x += v.x; ac.y += v.y; ac.z += v.z; ac.w += v.w;
            }
            const float dd = pv[d];
            float4 o;
            o.x = fmaxf(fmaf(ac.x, dd, bx), 0.f);
            o.y = fmaxf(fmaf(ac.y, dd, by), 0.f);
            o.z = fmaxf(fmaf(ac.z, dd, bz), 0.f);
            o.w = fmaxf(fmaf(ac.w, dd, bw), 0.f);
            *(float4*)&Bf[d * 16 + q * 4] = o;
        }
    }
    __syncthreads();

    // --- p[n] = h1[n].Wl ; score[n] = h1[n].Wr + sag_b ----------------------
    for (int n = tid; n < Nn; n += NT) {
        float pl = 0.f, pr = cst[48];
        #pragma unroll
        for (int m = 0; m < 16; m++) {
            const float h = Bf[n * 16 + m];
            pl = fmaf(h, cst[16 + m], pl);
            pr = fmaf(h, cst[32 + m], pr);
        }
        pv[n] = pl; score[n] = pr;
    }
    __syncthreads();

    // --- score[d] += sum p[srcs] ; sortable keys ------------------------------
    for (int d = tid; d < Nn; d += NT) {
        float s = score[d];
        const int e0 = off[d], e1 = off[d + 1];
        for (int j = e0; j < e1; j++) s += pv[srcs[j]];
        score[d] = s;
        unsigned u = __float_as_uint(s);
        u = (u & 0x80000000u) ? ~u : (u | 0x80000000u);
        keys[d] = ((unsigned long long)(~u) << 32) | (unsigned)d;
    }
    __syncthreads();

    // --- bitonic sort ----------------------------------------------------------
    for (int k = 2; k <= Nn; k <<= 1) {
        for (int j = k >> 1; j > 0; j >>= 1) {
            const int lo = ((tid & ~(j - 1)) << 1) | (tid & (j - 1));
            const int hi = lo + j;
            const unsigned long long a = keys[lo], b = keys[hi];
            const bool up = ((lo & k) == 0);
            if (up ? (a > b) : (a < b)) { keys[lo] = b; keys[hi] = a; }
            __syncthreads();
        }
    }

    // --- newidx + gate -----------------------------------------------------------
    for (int n = tid; n < Nn; n += NT) newidx[n] = -1;
    __syncthreads();
    float* tvf = (float*)cur;
    for (int r = tid; r < Kn; r += NT) {
        const int n = (int)(keys[r] & 0xFFFFFFFFull);
        newidx[n] = r;
        tvf[r] = tanhf(score[n]);
    }
    __syncthreads();
    for (int i = tid; i < Kn * 16; i += NT) {
        const int r = i >> 4, m = i & 15;
        const int n = (int)(keys[r] & 0xFFFFFFFFull);
        A[r * 16 + m] = Bf[n * 16 + m] * tvf[r];
    }
    __syncthreads();

    // --- deg2 over valid remapped edges -----------------------------------------
    for (int d = tid; d < Nn; d += NT) {
        const int nd = newidx[d];
        if (nd >= 0) {
            int c = 0;
            const int e0 = off[d], e1 = off[d + 1];
            for (int j = e0; j < e1; j++) c += (newidx[srcs[j]] >= 0);
            dinv2[nd] = rsqrtf(1.0f + (float)c);
        }
    }
    __syncthreads();
    for (int i = tid; i < Kn * 16; i += NT) A[i] *= dinv2[i >> 4];
    __syncthreads();

    // --- conv2 pre-aggregation (MID space) -> Bf rows [0,K) ----------------------
    {
        const int grp = tid >> 2, q = tid & 3;
        for (int d = grp; d < Nn; d += 128) {
            const int nd = newidx[d];
            if (nd < 0) continue;
            const int e0 = off[d], e1 = off[d + 1];
            float4 ac = *(const float4*)&A[nd * 16 + q * 4];
            for (int j = e0; j < e1; j++) {
                const int ns = newidx[srcs[j]];
                if (ns >= 0) {
                    const float4 v = *(const float4*)&A[ns * 16 + q * 4];
                    ac.x += v.x; ac.y += v.y; ac.z += v.z; ac.w += v.w;
                }
            }
            const float dd = dinv2[nd];
            *(float4*)&Bf[nd * 16 + q * 4] = make_float4(ac.x * dd, ac.y * dd, ac.z * dd, ac.w * dd);
        }
    }
    __syncthreads();

    // --- h2 = relu(pre @ W2 + b2), mean over K -> g_emb (f32x2, regs) ------------
    {
        const int cg = tid & 63, rb = tid >> 6;
        const int c0 = cg * 4;
        unsigned long long wreg[32];
        #pragma unroll
        for (int i = 0; i < 4; i++)
            #pragma unroll
            for (int k2 = 0; k2 < 8; k2++)
                wreg[i * 8 + k2] = pk2(w2s[(2 * k2) * Hn + c0 + i], w2s[(2 * k2 + 1) * Hn + c0 + i]);
        float biasv[4], accs[4];
        #pragma unroll
        for (int i = 0; i < 4; i++) { biasv[i] = b2s[c0 + i]; accs[i] = 0.f; }

        for (int r = rb; r < Kn; r += 8) {
            const ulonglong2* pr = (const ulonglong2*)&Bf[r * 16];
            const ulonglong2 v0 = pr[0], v1 = pr[1], v2 = pr[2], v3 = pr[3];
            #pragma unroll
            for (int i = 0; i < 4; i++) {
                unsigned long long dd_ = 0;
                dd_ = ffma2(v0.x, wreg[i * 8 + 0], dd_);
                dd_ = ffma2(v0.y, wreg[i * 8 + 1], dd_);
                dd_ = ffma2(v1.x, wreg[i * 8 + 2], dd_);
                dd_ = ffma2(v1.y, wreg[i * 8 + 3], dd_);
                dd_ = ffma2(v2.x, wreg[i * 8 + 4], dd_);
                dd_ = ffma2(v2.y, wreg[i * 8 + 5], dd_);
                dd_ = ffma2(v3.x, wreg[i * 8 + 6], dd_);
                dd_ = ffma2(v3.y, wreg[i * 8 + 7], dd_);
                accs[i] += fmaxf(hsum2(dd_) + biasv[i], 0.f);
            }
        }
        float* redf = (float*)keys;
        #pragma unroll
        for (int i = 0; i < 4; i++) redf[rb * 256 + c0 + i] = accs[i];
        __syncthreads();
        if (tid < 256) {
            float s = 0.f;
            #pragma unroll
            for (int rbi = 0; rbi < 8; rbi++) s += redf[rbi * 256 + tid];
            g_emb[(size_t)g * Hn + tid] = s * (1.0f / (float)Kn);
        }
    }
}

// =====================================================================
// K2: LSTM, NO clusters. 128 plain CTAs: CTA = (batch b, rank r).
// CTA owns hidden units [32r,32r+32) of batch b; weights in registers.
// Per-step h exchange through L2 with per-(batch,step) counters.
// =====================================================================
__global__ __launch_bounds__(512) void k_lstm(
    const float* __restrict__ W_ih, const float* __restrict__ b_ih,
    const float* __restrict__ b_hh, const float* __restrict__ W_hh,
    const float* __restrict__ cls_W, const float* __restrict__ cls_b,
    float* __restrict__ out)
{
    __shared__ float hsb[2 * 288];        // [buf][(k>>5)*36 + (k&31)]
    __shared__ float iht[Tn * 32 * 4];    // [(t*32+hu_l)*4 + gate]
    __shared__ float embt[Tn * 260];      // emb rows for this batch
    __shared__ float bsm[128];

    const int tid  = threadIdx.x;
    const int b    = blockIdx.x >> 3;     // batch
    const int rank = blockIdx.x & 7;      // hidden-unit block
    const int kc = tid & 7;               // k-chunk [32kc, 32kc+32)
    const int jp = tid >> 3;              // rows {2jp, 2jp+1}
    const int q0 = 2 * jp, q1 = 2 * jp + 1;
    const int j0 = (q0 & 3) * Hn + rank * 32 + (q0 >> 2);
    const int j1 = (q1 & 3) * Hn + rank * 32 + (q1 >> 2);

    // --- stage emb rows for this batch: graph g = t*16 + b -------------------
    for (int idx = tid; idx < Tn * Hn; idx += 512) {
        const int t = idx >> 8, k = idx & 255;
        embt[t * 260 + k] = g_emb[(size_t)(t * Bn + b) * Hn + k];
    }
    if (tid < 128) bsm[tid] = b_ih[(tid & 3) * Hn + rank * 32 + (tid >> 2)]
                            + b_hh[(tid & 3) * Hn + rank * 32 + (tid >> 2)];
    for (int i = tid; i < 288; i += 512) hsb[i] = 0.f;   // buf0 = h(0) = 0

    unsigned long long wA[16], wB[16];
    // --- phase 1: wA/wB = W_ih rows; compute iht ------------------------------
    {
        const float* r0 = W_ih + (size_t)j0 * Hn + kc * 32;
        const float* r1 = W_ih + (size_t)j1 * Hn + kc * 32;
        #pragma unroll
        for (int i = 0; i < 16; i++) {
            wA[i] = pk2(r0[2 * i], r0[2 * i + 1]);
            wB[i] = pk2(r1[2 * i], r1[2 * i + 1]);
        }
    }
    __syncthreads();
    for (int t = 0; t < Tn; t++) {
        const ulonglong2* ev = (const ulonglong2*)&embt[t * 260 + kc * 32];
        unsigned long long aA = 0, aB = 0;
        #pragma unroll
        for (int i2 = 0; i2 < 8; i2++) {
            const ulonglong2 e2 = ev[i2];
            aA = ffma2(e2.x, wA[2 * i2],     aA);
            aA = ffma2(e2.y, wA[2 * i2 + 1], aA);
            aB = ffma2(e2.x, wB[2 * i2],     aB);
            aB = ffma2(e2.y, wB[2 * i2 + 1], aB);
        }
        float fA = hsum2(aA), fB = hsum2(aB);
        fA += __shfl_xor_sync(0xFFFFFFFFu, fA, 1);
        fA += __shfl_xor_sync(0xFFFFFFFFu, fA, 2);
        fA += __shfl_xor_sync(0xFFFFFFFFu, fA, 4);
        fB += __shfl_xor_sync(0xFFFFFFFFu, fB, 1);
        fB += __shfl_xor_sync(0xFFFFFFFFu, fB, 2);
        fB += __shfl_xor_sync(0xFFFFFFFFu, fB, 4);
        if (kc == 0) {
            iht[(t * 32 + (q0 >> 2)) * 4 + (q0 & 3)] = fA + bsm[q0];
            iht[(t * 32 + (q1 >> 2)) * 4 + (q1 & 3)] = fB + bsm[q1];
        }
    }

    // --- phase 2: wA/wB = W_hh rows -------------------------------------------
    {
        const float* r0 = W_hh + (size_t)j0 * Hn + kc * 32;
        const float* r1 = W_hh + (size_t)j1 * Hn + kc * 32;
        #pragma unroll
        for (int i = 0; i < 16; i++) {
            wA[i] = pk2(r0[2 * i], r0[2 * i + 1]);
            wB[i] = pk2(r1[2 * i], r1[2 * i + 1]);
        }
    }
    __syncthreads();

    const int lane = tid & 31;
    const int warp = tid >> 5;
    const bool epi = ((lane & 15) == 0);           // lanes 0 and 16
    const int  ehu = 2 * warp + (lane >> 4);       // local hidden unit
    float creg = 0.f;

    for (int t = 0; t < Tn; t++) {
        const ulonglong2* hv = (const ulonglong2*)&hsb[(t & 1) * 288 + kc * 36];
        unsigned long long aA = 0, aB = 0;
        #pragma unroll
        for (int i2 = 0; i2 < 8; i2++) {
            const ulonglong2 h2 = hv[i2];
            aA = ffma2(h2.x, wA[2 * i2],     aA);
            aA = ffma2(h2.y, wA[2 * i2 + 1], aA);
            aB = ffma2(h2.x, wB[2 * i2],     aB);
            aB = ffma2(h2.y, wB[2 * i2 + 1], aB);
        }
        float fA = hsum2(aA), fB = hsum2(aB);
        fA += __shfl_xor_sync(0xFFFFFFFFu, fA, 1);
        fA += __shfl_xor_sync(0xFFFFFFFFu, fA, 2);
        fA += __shfl_xor_sync(0xFFFFFFFFu, fA, 4);
        fB += __shfl_xor_sync(0xFFFFFFFFu, fB, 1);
        fB += __shfl_xor_sync(0xFFFFFFFFu, fB, 2);
        fB += __shfl_xor_sync(0xFFFFFFFFu, fB, 4);

        // gather 4 gates to lanes 0 (hu 2w) and 16 (hu 2w+1)
        const int base = lane & 16;
        const float gi = __shfl_sync(0xFFFFFFFFu, fA, base);
        const float gf = __shfl_sync(0xFFFFFFFFu, fB, base);
        const float gg = __shfl_sync(0xFFFFFFFFu, fA, base + 8);
        const float go = __shfl_sync(0xFFFFFFFFu, fB, base + 8);

        if (epi) {
            const float4 ihv = *(const float4*)&iht[(t * 32 + ehu) * 4];
            creg = sigmoidf_(gf + ihv.y) * creg + sigmoidf_(gi + ihv.x) * tanhf(gg + ihv.z);
            const float hn = sigmoidf_(go + ihv.w) * tanhf(creg);
            __stcg(&g_h[((t + 1) & 1) * (Bn * Hn) + b * Hn + rank * 32 + ehu], hn);
            __threadfence();
        }
        __syncthreads();
        if (tid == 0) {
            atomicAdd(&g_cnt[b * Tn + t], 1u);
            unsigned v;
            do {
                asm volatile("ld.global.acquire.gpu.u32 %0,[%1];"
                             : "=r"(v) : "l"(&g_cnt[b * Tn + t]));
            } while (v < 8u);
        }
        __syncthreads();

        if (t < Tn - 1) {
            if (tid < 64) {
                const float4 hvv = __ldcg((const float4*)
                    &g_h[((t + 1) & 1) * (Bn * Hn) + b * Hn + tid * 4]);
                *(float4*)&hsb[((t + 1) & 1) * 288 + (tid >> 3) * 36 + (tid & 7) * 4] = hvv;
            }
            __syncthreads();
        }
    }

    // classifier: rank-0 CTA of each batch; final h(16) lives in g_h buf 0
    if (rank == 0 && tid < 32) {
        float p = 0.f;
        #pragma unroll
        for (int i = 0; i < 8; i++)
            p += __ldcg(&g_h[0 * (Bn * Hn) + b * Hn + i * 32 + tid])
                 * __ldg(&cls_W[i * 32 + tid]);
        #pragma unroll
        for (int o = 16; o; o >>= 1) p += __shfl_xor_sync(0xFFFFFFFFu, p, o);
        if (tid == 0) out[b] = p + cls_b[0];
    }
}

// =====================================================================
extern "C" void kernel_launch(void* const* d_in, const int* in_sizes, int n_in,
                              void* d_out, int out_size)
{
    (void)in_sizes; (void)n_in; (void)out_size;
    const float* x     = (const float*)d_in[0];
    const int*   ei    = (const int*)  d_in[1];
    const float* W1    = (const float*)d_in[2];
    const float* b1    = (const float*)d_in[3];
    const float* Wl    = (const float*)d_in[4];
    const float* Wr    = (const float*)d_in[5];
    const float* sb    = (const float*)d_in[6];
    const float* W2    = (const float*)d_in[7];
    const float* b2    = (const float*)d_in[8];
    const float* W_ih  = (const float*)d_in[9];
    const float* W_hh  = (const float*)d_in[10];
    const float* b_ih  = (const float*)d_in[11];
    const float* b_hh  = (const float*)d_in[12];
    const float* cls_W = (const float*)d_in[13];
    const float* cls_b = (const float*)d_in[14];
    float* out = (float*)d_out;

    const size_t smem1 = 55620 * sizeof(float);  // 222480 B
    cudaFuncSetAttribute(k_embed, cudaFuncAttributeMaxDynamicSharedMemorySize, (int)smem1);

    k_embed<<<NG, NT, smem1>>>(x, ei, W1, b1, Wl, Wr, sb, W2, b2);
    k_lstm <<<128, 512>>>(W_ih, b_ih, b_hh, W_hh, cls_W, cls_b, out);
}

// round 11
// speedup vs baseline: 1.4381x; 1.0241x over previous
#include <cuda_runtime.h>
#include <cstdint>

#define NT 512
constexpr int Tn  = 16;
constexpr int Bn  = 16;
constexpr int Nn  = 1024;
constexpr int En  = 16384;
constexpr int Fin = 128;
constexpr int Hn  = 256;
constexpr int Kn  = 820;
constexpr int NG  = Tn * Bn;   // 256 graphs

// ---------------- global scratch ----------------
__device__ float    g_emb[NG * Hn];
__device__ float    g_ihpre[NG * 4 * Hn];  // [g][j], j = gate*256 + hu (bias folded)
__device__ float    g_h[2 * Bn * Hn];      // double-buffered hidden state
__device__ unsigned g_cnt[Bn * Tn];        // per-batch per-step arrival counters

__device__ __forceinline__ float sigmoidf_(float v) { return 1.0f / (1.0f + expf(-v)); }

// ---------------- f32x2 helpers ----------------
__device__ __forceinline__ unsigned long long pk2(float a, float b) {
    unsigned long long r; asm("mov.b64 %0,{%1,%2};" : "=l"(r) : "f"(a), "f"(b)); return r;
}
__device__ __forceinline__ float2 upk(unsigned long long v) {
    float2 o; asm("mov.b64 {%0,%1},%2;" : "=f"(o.x), "=f"(o.y) : "l"(v)); return o;
}
__device__ __forceinline__ unsigned long long ffma2(unsigned long long a, unsigned long long b, unsigned long long c) {
    unsigned long long d; asm("fma.rn.f32x2 %0,%1,%2,%3;" : "=l"(d) : "l"(a), "l"(b), "l"(c)); return d;
}
__device__ __forceinline__ float hsum2(unsigned long long v) { float2 o = upk(v); return o.x + o.y; }

// conv1 half (f32x2): 256 threads (gt in [0,256)), nodes [pb, pb+512)
__device__ __forceinline__ void conv1_half(const float* __restrict__ xg,
                                           const unsigned long long* w1p,
                                           float* A, int gt, int pb)
{
    const int mq = gt & 3;
    const int nb = gt >> 2;
    const int c0 = mq * 4;
    for (int n = pb + nb; n < pb + 512; n += 64) {
        unsigned long long a0 = 0, a1 = 0, a2 = 0, a3 = 0;
        const ulonglong2* xr = (const ulonglong2*)(xg + (size_t)n * Fin);
        #pragma unroll 8
        for (int i = 0; i < 32; i++) {
            const ulonglong2 xv = xr[i];
            const ulonglong2* wp = (const ulonglong2*)&w1p[(2 * i) * 16 + c0];
            const ulonglong2* wq = (const ulonglong2*)&w1p[(2 * i + 1) * 16 + c0];
            const ulonglong2 wa = wp[0], wb = wp[1];
            const ulonglong2 wc = wq[0], wd = wq[1];
            a0 = ffma2(xv.x, wa.x, a0); a1 = ffma2(xv.x, wa.y, a1);
            a2 = ffma2(xv.x, wb.x, a2); a3 = ffma2(xv.x, wb.y, a3);
            a0 = ffma2(xv.y, wc.x, a0); a1 = ffma2(xv.y, wc.y, a1);
            a2 = ffma2(xv.y, wd.x, a2); a3 = ffma2(xv.y, wd.y, a3);
        }
        *(float4*)&A[n * 16 + c0] = make_float4(hsum2(a0), hsum2(a1), hsum2(a2), hsum2(a3));
    }
}

// =====================================================================
// K1: per-graph embedding. One CTA per graph. (verified R10 body)
// =====================================================================
__global__ __launch_bounds__(NT) void k_embed(
    const float* __restrict__ x, const int* __restrict__ ei,
    const float* __restrict__ W1, const float* __restrict__ b1,
    const float* __restrict__ Wl, const float* __restrict__ Wr,
    const float* __restrict__ sb,
    const float* __restrict__ W2, const float* __restrict__ b2)
{
    extern __shared__ float sm[];
    float*              A      = sm;                                 // [0,16384)
    float*              Bf     = sm + 16384;                         // [16384,32768)
    unsigned long long* keys   = (unsigned long long*)(sm + 32768);  // 1024 u64
    unsigned short*     srcs   = (unsigned short*)(sm + 34816);      // 16384 u16
    int*                off    = (int*)(sm + 43008);                 // 1028
    int*                cur    = (int*)(sm + 44036);                 // 1024
    float*              pv     = sm + 45060;                         // 1024
    float*              score  = sm + 46084;                         // 1024
    int*                newidx = (int*)(sm + 47108);                 // 1024
    float*              dinv2  = sm + 48132;                         // 1024
    unsigned long long* w1p    = (unsigned long long*)(sm + 49156);  // 1024 u64
    float*              w2s    = sm + 51204;                         // 4096 (aliases tmppos)
    unsigned char*      tmppos = (unsigned char*)(sm + 51204);       // 16384 u8
    float*              b2s    = sm + 55300;                         // 256
    float*              cst    = sm + 55556;                         // 64
    // total 55620 floats = 222480 B

    const int tid = threadIdx.x;
    const int g   = blockIdx.x;
    const float* xg   = x  + (size_t)g * Nn * Fin;
    const int*   srcp = ei + (size_t)g * 2 * En;
    const int*   dstp = srcp + En;

    for (int i = tid; i < 1024; i += NT) {
        const int f2 = i >> 4, c = i & 15;
        w1p[i] = pk2(W1[(2 * f2) * 16 + c], W1[(2 * f2 + 1) * 16 + c]);
    }
    if (tid < 16) { cst[tid] = b1[tid]; cst[16 + tid] = Wl[tid]; cst[32 + tid] = Wr[tid]; }
    if (tid == 0) cst[48] = sb[0];
    for (int i = tid; i < Nn; i += NT) cur[i] = 0;
    if (g == 0 && tid < Bn * Tn) g_cnt[tid] = 0u;
    __syncthreads();

    // --- phase A: warps 0-7 conv1 nodes [0,512) || warps 8-15 histogram+rank
    if (tid < 256) {
        conv1_half(xg, w1p, A, tid, 0);
    } else {
        for (int e = tid - 256; e < En; e += 256)
            tmppos[e] = (unsigned char)atomicAdd(&cur[dstp[e]], 1);
    }
    __syncthreads();

    // --- exclusive Blelloch scan of counts -> off[0..1024] ------------------
    for (int i = tid; i < Nn; i += NT) off[i] = cur[i];
    for (int d2 = 1; d2 < Nn; d2 <<= 1) {
        __syncthreads();
        const int idx = (tid + 1) * (d2 << 1) - 1;
        if (idx < Nn) off[idx] += off[idx - d2];
    }
    __syncthreads();
    if (tid == 0) { off[Nn] = off[Nn - 1]; off[Nn - 1] = 0; }
    for (int d2 = Nn >> 1; d2 >= 1; d2 >>= 1) {
        __syncthreads();
        const int idx = (tid + 1) * (d2 << 1) - 1;
        if (idx < Nn) { const int t = off[idx - d2]; off[idx - d2] = off[idx]; off[idx] += t; }
    }
    __syncthreads();
    for (int i = tid; i < Nn; i += NT)
        pv[i] = rsqrtf(1.0f + (float)(off[i + 1] - off[i]));   // dinv
    __syncthreads();

    // --- phase C: warps 0-7 conv1 nodes [512,1024) || warps 8-15 placement --
    if (tid < 256) {
        conv1_half(xg, w1p, A, tid, 512);
    } else {
        for (int e = tid - 256; e < En; e += 256)
            srcs[off[dstp[e]] + tmppos[e]] = (unsigned short)srcp[e];
    }
    __syncthreads();

    // tmppos dead -> load W2/b2 into its alias; pre-scale A rows by dinv
    for (int i = tid; i < 16 * Hn; i += NT) w2s[i] = W2[i];
    for (int i = tid; i < Hn; i += NT) b2s[i] = b2[i];
    for (int i = tid; i < Nn * 16; i += NT) A[i] *= pv[i >> 4];
    __syncthreads();

    // --- conv1 gather (pure sum, self included) + bias + relu -> Bf = h1 ----
    {
        const int grp = tid >> 2, q = tid & 3;
        const float bx = cst[q * 4 + 0], by = cst[q * 4 + 1];
        const float bz = cst[q * 4 + 2], bw = cst[q * 4 + 3];
        for (int d = grp; d < Nn; d += 128) {
            const int e0 = off[d], e1 = off[d + 1];
            float4 ac = *(const float4*)&A[d * 16 + q * 4];
            for (int j = e0; j < e1; j++) {
                const float4 v = *(const float4*)&A[srcs[j] * 16 + q * 4];
                ac.x += v.x; ac.y += v.y; ac.z += v.z; ac.w += v.w;
            }
            const float dd = pv[d];
            float4 o;
            o.x = fmaxf(fmaf(ac.x, dd, bx), 0.f);
            o.y = fmaxf(fmaf(ac.y, dd, by), 0.f);
            o.z = fmaxf(fmaf(ac.z, dd, bz), 0.f);
            o.w = fmaxf(fmaf(ac.w, dd, bw), 0.f);
            *(float4*)&Bf[d * 16 + q * 4] = o;
        }
    }
    __syncthreads();

    // --- p[n] = h1[n].Wl ; score[n] = h1[n].Wr + sag_b ----------------------
    for (int n = tid; n < Nn; n += NT) {
        float pl = 0.f, pr = cst[48];
        #pragma unroll
        for (int m = 0; m < 16; m++) {
            const float h = Bf[n * 16 + m];
            pl = fmaf(h, cst[16 + m], pl);
            pr = fmaf(h, cst[32 + m], pr);
        }
        pv[n] = pl; score[n] = pr;
    }
    __syncthreads();

    // --- score[d] += sum p[srcs] ; sortable keys ------------------------------
    for (int d = tid; d < Nn; d += NT) {
        float s = score[d];
        const int e0 = off[d], e1 = off[d + 1];
        for (int j = e0; j < e1; j++) s += pv[srcs[j]];
        score[d] = s;
        unsigned u = __float_as_uint(s);
        u = (u & 0x80000000u) ? ~u : (u | 0x80000000u);
        keys[d] = ((unsigned long long)(~u) << 32) | (unsigned)d;
    }
    __syncthreads();

    // --- bitonic sort ----------------------------------------------------------
    for (int k = 2; k <= Nn; k <<= 1) {
        for (int j = k >> 1; j > 0; j >>= 1) {
            const int lo = ((tid & ~(j - 1)) << 1) | (tid & (j - 1));
            const int hi = lo + j;
            const unsigned long long a = keys[lo], b = keys[hi];
            const bool up = ((lo & k) == 0);
            if (up ? (a > b) : (a < b)) { keys[lo] = b; keys[hi] = a; }
            __syncthreads();
        }
    }

    // --- newidx + gate -----------------------------------------------------------
    for (int n = tid; n < Nn; n += NT) newidx[n] = -1;
    __syncthreads();
    float* tvf = (float*)cur;
    for (int r = tid; r < Kn; r += NT) {
        const int n = (int)(keys[r] & 0xFFFFFFFFull);
        newidx[n] = r;
        tvf[r] = tanhf(score[n]);
    }
    __syncthreads();
    for (int i = tid; i < Kn * 16; i += NT) {
        const int r = i >> 4, m = i & 15;
        const int n = (int)(keys[r] & 0xFFFFFFFFull);
        A[r * 16 + m] = Bf[n * 16 + m] * tvf[r];
    }
    __syncthreads();

    // --- deg2 over valid remapped edges -----------------------------------------
    for (int d = tid; d < Nn; d += NT) {
        const int nd = newidx[d];
        if (nd >= 0) {
            int c = 0;
            const int e0 = off[d], e1 = off[d + 1];
            for (int j = e0; j < e1; j++) c += (newidx[srcs[j]] >= 0);
            dinv2[nd] = rsqrtf(1.0f + (float)c);
        }
    }
    __syncthreads();
    for (int i = tid; i < Kn * 16; i += NT) A[i] *= dinv2[i >> 4];
    __syncthreads();

    // --- conv2 pre-aggregation (MID space) -> Bf rows [0,K) ----------------------
    {
        const int grp = tid >> 2, q = tid & 3;
        for (int d = grp; d < Nn; d += 128) {
            const int nd = newidx[d];
            if (nd < 0) continue;
            const int e0 = off[d], e1 = off[d + 1];
            float4 ac = *(const float4*)&A[nd * 16 + q * 4];
            for (int j = e0; j < e1; j++) {
                const int ns = newidx[srcs[j]];
                if (ns >= 0) {
                    const float4 v = *(const float4*)&A[ns * 16 + q * 4];
                    ac.x += v.x; ac.y += v.y; ac.z += v.z; ac.w += v.w;
                }
            }
            const float dd = dinv2[nd];
            *(float4*)&Bf[nd * 16 + q * 4] = make_float4(ac.x * dd, ac.y * dd, ac.z * dd, ac.w * dd);
        }
    }
    __syncthreads();

    // --- h2 = relu(pre @ W2 + b2), mean over K -> g_emb (f32x2, regs) ------------
    {
        const int cg = tid & 63, rb = tid >> 6;
        const int c0 = cg * 4;
        unsigned long long wreg[32];
        #pragma unroll
        for (int i = 0; i < 4; i++)
            #pragma unroll
            for (int k2 = 0; k2 < 8; k2++)
                wreg[i * 8 + k2] = pk2(w2s[(2 * k2) * Hn + c0 + i], w2s[(2 * k2 + 1) * Hn + c0 + i]);
        float biasv[4], accs[4];
        #pragma unroll
        for (int i = 0; i < 4; i++) { biasv[i] = b2s[c0 + i]; accs[i] = 0.f; }

        for (int r = rb; r < Kn; r += 8) {
            const ulonglong2* pr = (const ulonglong2*)&Bf[r * 16];
            const ulonglong2 v0 = pr[0], v1 = pr[1], v2 = pr[2], v3 = pr[3];
            #pragma unroll
            for (int i = 0; i < 4; i++) {
                unsigned long long dd_ = 0;
                dd_ = ffma2(v0.x, wreg[i * 8 + 0], dd_);
                dd_ = ffma2(v0.y, wreg[i * 8 + 1], dd_);
                dd_ = ffma2(v1.x, wreg[i * 8 + 2], dd_);
                dd_ = ffma2(v1.y, wreg[i * 8 + 3], dd_);
                dd_ = ffma2(v2.x, wreg[i * 8 + 4], dd_);
                dd_ = ffma2(v2.y, wreg[i * 8 + 5], dd_);
                dd_ = ffma2(v3.x, wreg[i * 8 + 6], dd_);
                dd_ = ffma2(v3.y, wreg[i * 8 + 7], dd_);
                accs[i] += fmaxf(hsum2(dd_) + biasv[i], 0.f);
            }
        }
        float* redf = (float*)keys;
        #pragma unroll
        for (int i = 0; i < 4; i++) redf[rb * 256 + c0 + i] = accs[i];
        __syncthreads();
        if (tid < 256) {
            float s = 0.f;
            #pragma unroll
            for (int rbi = 0; rbi < 8; rbi++) s += redf[rbi * 256 + tid];
            g_emb[(size_t)g * Hn + tid] = s * (1.0f / (float)Kn);
        }
    }
}

// =====================================================================
// K2: ihpre[g][j] = emb[g].W_ih[j] + b_ih[j] + b_hh[j]; 64 CTAs x 16 rows
// (verified R6 kernel)
// =====================================================================
__global__ __launch_bounds__(256) void k_prep(
    const float* __restrict__ W_ih, const float* __restrict__ b_ih,
    const float* __restrict__ b_hh)
{
    __shared__ float wih[16 * 260];
    __shared__ float embt[16 * 260];
    __shared__ float bs[16];
    const int tid = threadIdx.x;
    const int j0  = blockIdx.x * 16;

    for (int idx = tid; idx < 16 * 256; idx += 256)
        wih[(idx >> 8) * 260 + (idx & 255)] = W_ih[(size_t)(j0 + (idx >> 8)) * Hn + (idx & 255)];
    if (tid < 16) bs[tid] = b_ih[j0 + tid] + b_hh[j0 + tid];
    __syncthreads();

    const int rl = tid & 15, gl = tid >> 4;
    for (int tile = 0; tile < 16; tile++) {
        const int gb = tile * 16;
        for (int idx = tid; idx < 16 * 256; idx += 256)
            embt[(idx >> 8) * 260 + (idx & 255)] = g_emb[(size_t)(gb + (idx >> 8)) * Hn + (idx & 255)];
        __syncthreads();
        unsigned long long acc = 0;
        const ulonglong2* ev = (const ulonglong2*)&embt[gl * 260];
        const ulonglong2* wv = (const ulonglong2*)&wih[rl * 260];
        #pragma unroll 8
        for (int k4 = 0; k4 < 64; k4++) {
            const ulonglong2 e = ev[k4], w = wv[k4];
            acc = ffma2(e.x, w.x, acc);
            acc = ffma2(e.y, w.y, acc);
        }
        g_ihpre[(size_t)(gb + gl) * 1024 + j0 + rl] = hsum2(acc) + bs[rl];
        __syncthreads();
    }
}

// =====================================================================
// K3: LSTM recurrence. 128 plain CTAs: CTA = (batch b, rank r), owns
// hidden units [32r,32r+32). W_hh staged coalesced -> registers.
// Per-step: stcg h -> syncthreads -> tid0 red.release -> 64 threads
// poll-acquire + reload h. No membar, no cluster.
// =====================================================================
__global__ __launch_bounds__(512) void k_lstm(
    const float* __restrict__ W_hh, const float* __restrict__ cls_W,
    const float* __restrict__ cls_b, float* __restrict__ out)
{
    __shared__ float hsb[2 * 288];        // [buf][(k>>5)*36 + (k&31)]
    __shared__ float iht[Tn * 32 * 4];    // [(t*32+hu_l)*4 + gate]
    __shared__ float wbuf[32 * 264];      // staging for one gate block
    const int tid  = threadIdx.x;
    const int b    = blockIdx.x >> 3;     // batch
    const int rank = blockIdx.x & 7;      // hidden-unit block
    const int kc = tid & 7;               // k-chunk [32kc, 32kc+32)
    const int jp = tid >> 3;              // rows {2jp, 2jp+1}
    const int q0 = 2 * jp, q1 = 2 * jp + 1;

    // --- stage iht slice: gates for this CTA's 32 units, all 16 steps --------
    for (int idx = tid; idx < Tn * 32 * 4; idx += 512) {
        const int t = idx >> 7, gate = (idx >> 5) & 3, hu = idx & 31;
        iht[(t * 32 + hu) * 4 + gate] =
            g_ihpre[(size_t)(t * Bn + b) * 1024 + gate * 256 + rank * 32 + hu];
    }
    for (int i = tid; i < 288; i += 512) hsb[i] = 0.f;   // buf0 = h(0) = 0

    // --- W_hh -> registers via coalesced smem staging, one gate block at a time
    unsigned long long wA[16], wB[16];
    #pragma unroll
    for (int gblk = 0; gblk < 4; gblk++) {
        __syncthreads();
        const float* src = W_hh + (size_t)(gblk * 256 + rank * 32) * Hn;  // 32 rows, 32KB contiguous
        for (int idx = tid; idx < 2048; idx += 512) {     // 2048 float4
            const int r = idx >> 6, c4 = idx & 63;
            *(float4*)&wbuf[r * 264 + c4 * 4] = __ldg((const float4*)&src[r * 256 + c4 * 4]);
        }
        __syncthreads();
        if ((q0 & 3) == gblk) {
            const int m = q0 >> 2;
            #pragma unroll
            for (int i = 0; i < 16; i++)
                wA[i] = pk2(wbuf[m * 264 + kc * 32 + 2 * i], wbuf[m * 264 + kc * 32 + 2 * i + 1]);
        }
        if ((q1 & 3) == gblk) {
            const int m = q1 >> 2;
            #pragma unroll
            for (int i = 0; i < 16; i++)
                wB[i] = pk2(wbuf[m * 264 + kc * 32 + 2 * i], wbuf[m * 264 + kc * 32 + 2 * i + 1]);
        }
    }
    __syncthreads();

    const int lane = tid & 31;
    const int warp = tid >> 5;
    const bool epi = ((lane & 15) == 0);           // lanes 0 and 16
    const int  ehu = 2 * warp + (lane >> 4);       // local hidden unit
    float creg = 0.f;

    for (int t = 0; t < Tn; t++) {
        const ulonglong2* hv = (const ulonglong2*)&hsb[(t & 1) * 288 + kc * 36];
        unsigned long long aA = 0, aB = 0;
        #pragma unroll
        for (int i2 = 0; i2 < 8; i2++) {
            const ulonglong2 h2 = hv[i2];
            aA = ffma2(h2.x, wA[2 * i2],     aA);
            aA = ffma2(h2.y, wA[2 * i2 + 1], aA);
            aB = ffma2(h2.x, wB[2 * i2],     aB);
            aB = ffma2(h2.y, wB[2 * i2 + 1], aB);
        }
        float fA = hsum2(aA), fB = hsum2(aB);
        fA += __shfl_xor_sync(0xFFFFFFFFu, fA, 1);
        fA += __shfl_xor_sync(0xFFFFFFFFu, fA, 2);
        fA += __shfl_xor_sync(0xFFFFFFFFu, fA, 4);
        fB += __shfl_xor_sync(0xFFFFFFFFu, fB, 1);
        fB += __shfl_xor_sync(0xFFFFFFFFu, fB, 2);
        fB += __shfl_xor_sync(0xFFFFFFFFu, fB, 4);

        // gather 4 gates to lanes 0 (hu 2w) and 16 (hu 2w+1)
        const int base = lane & 16;
        const float gi = __shfl_sync(0xFFFFFFFFu, fA, base);
        const float gf = __shfl_sync(0xFFFFFFFFu, fB, base);
        const float gg = __shfl_sync(0xFFFFFFFFu, fA, base + 8);
        const float go = __shfl_sync(0xFFFFFFFFu, fB, base + 8);

        if (epi) {
            const float4 ihv = *(const float4*)&iht[(t * 32 + ehu) * 4];
            creg = sigmoidf_(gf + ihv.y) * creg + sigmoidf_(gi + ihv.x) * tanhf(gg + ihv.z);
            const float hn = sigmoidf_(go + ihv.w) * tanhf(creg);
            __stcg(&g_h[((t + 1) & 1) * (Bn * Hn) + b * Hn + rank * 32 + ehu], hn);
        }
        __syncthreads();   // CTA-wide HB: all h stores ordered before tid0's release

        if (tid == 0)
            asm volatile("red.release.gpu.global.add.u32 [%0], %1;"
                         :: "l"(&g_cnt[b * Tn + t]), "r"(1u) : "memory");
        if (tid < 64) {
            unsigned v;
            do {
                asm volatile("ld.global.acquire.gpu.u32 %0,[%1];"
                             : "=r"(v) : "l"(&g_cnt[b * Tn + t]));
            } while (v < 8u);
            if (t < Tn - 1) {
                const float4 hvv = __ldcg((const float4*)
                    &g_h[((t + 1) & 1) * (Bn * Hn) + b * Hn + tid * 4]);
                *(float4*)&hsb[((t + 1) & 1) * 288 + (tid >> 3) * 36 + (tid & 7) * 4] = hvv;
            }
        }
        __syncthreads();
    }

    // classifier: rank-0 CTA of each batch; final h(16) lives in g_h buf 0
    // (tid<32 threads did their own acquire-poll at t=15)
    if (rank == 0 && tid < 32) {
        float p = 0.f;
        #pragma unroll
        for (int i = 0; i < 8; i++)
            p += __ldcg(&g_h[0 * (Bn * Hn) + b * Hn + i * 32 + tid])
                 * __ldg(&cls_W[i * 32 + tid]);
        #pragma unroll
        for (int o = 16; o; o >>= 1) p += __shfl_xor_sync(0xFFFFFFFFu, p, o);
        if (tid == 0) out[b] = p + cls_b[0];
    }
}

// =====================================================================
extern "C" void kernel_launch(void* const* d_in, const int* in_sizes, int n_in,
                              void* d_out, int out_size)
{
    (void)in_sizes; (void)n_in; (void)out_size;
    const float* x     = (const float*)d_in[0];
    const int*   ei    = (const int*)  d_in[1];
    const float* W1    = (const float*)d_in[2];
    const float* b1    = (const float*)d_in[3];
    const float* Wl    = (const float*)d_in[4];
    const float* Wr    = (const float*)d_in[5];
    const float* sb    = (const float*)d_in[6];
    const float* W2    = (const float*)d_in[7];
    const float* b2    = (const float*)d_in[8];
    const float* W_ih  = (const float*)d_in[9];
    const float* W_hh  = (const float*)d_in[10];
    const float* b_ih  = (const float*)d_in[11];
    const float* b_hh  = (const float*)d_in[12];
    const float* cls_W = (const float*)d_in[13];
    const float* cls_b = (const float*)d_in[14];
    float* out = (float*)d_out;

    const size_t smem1 = 55620 * sizeof(float);  // 222480 B
    cudaFuncSetAttribute(k_embed, cudaFuncAttributeMaxDynamicSharedMemorySize, (int)smem1);

    k_embed<<<NG, NT, smem1>>>(x, ei, W1, b1, Wl, Wr, sb, W2, b2);
    k_prep <<<64, 256>>>(W_ih, b_ih, b_hh);
    k_lstm <<<128, 512>>>(W_hh, cls_W, cls_b, out);
}